// round 8
// baseline (speedup 1.0000x reference)
#include <cuda_runtime.h>

// PINN via tabulated jets, cooperative-quad interpolation, 2 pts/quad/iter.
// Kernel A: order-6 jets (fp32, MUFU tanh) at 1025 nodes (h=2^-10), padded
// to 64B/node in 4 overlapping float4 groups. Kernel B: 4 lanes per point,
// one LDG.128 per lane fetches the node; magic-number rounding; each lane
// emits 2 of the 8 outputs. Outputs: [u,u_x,u_xx,w,w_x,w_xx,w_xxx,w_xxxx].

#define KNODES 1025
#define HINV   1024.0f
#define HF     0.0009765625f     // 2^-10 exact
#define MAGIC  12582912.0f       // 1.5 * 2^23

// node j: g0=(u0,u1,u2,u3) g1=(u3,u4,w0,w1) g2=(w1,w2,w3,w4) g3=(w3,w4,w5,w6)
__device__ float4 g_table4[KNODES * 4];

__device__ __forceinline__ float tanh_fast(float z, float& s) {
    float e, r;
    asm("ex2.approx.f32 %0, %1;" : "=f"(e) : "f"(z * 2.8853900817779268f));
    asm("rcp.approx.f32 %0, %1;" : "=f"(r) : "f"(e + 1.0f));
    float t = fmaf(-2.0f, r, 1.0f);
    s = fmaf(-t, t, 1.0f);
    return t;
}

// ---------------- Kernel A: order-6 jets at nodes ----------------

__global__ void pinn_build_table(const float* __restrict__ gW0, const float* __restrict__ gb0,
                                 const float* __restrict__ gW1, const float* __restrict__ gb1,
                                 const float* __restrict__ gW2, const float* __restrict__ gb2)
{
    int j = blockIdx.x * blockDim.x + threadIdx.x;
    if (j >= KNODES) return;

    const float x0 = (float)j * HF;

    float h[7][8];
#pragma unroll
    for (int k = 0; k < 8; ++k) {
        float w = gW0[k];
        float z = fmaf(w, x0, gb0[k]);
        float s;
        float t = tanh_fast(z, s);
        float t2 = t * t;
        float d2 = -2.0f * t * s;
        float d3 = s * (6.0f * t2 - 2.0f);
        float d4 = t * s * (16.0f - 24.0f * t2);
        float d5 = s * (16.0f + t2 * (-120.0f + 120.0f * t2));
        float d6 = s * t * (-272.0f + t2 * (960.0f - 720.0f * t2));
        float w2 = w * w, w3 = w2 * w;
        h[0][k] = t;
        h[1][k] = s  * w;
        h[2][k] = d2 * w2;
        h[3][k] = d3 * w3;
        h[4][k] = d4 * w2 * w2;
        h[5][k] = d5 * w2 * w3;
        h[6][k] = d6 * w3 * w3;
    }

    float u[5]; float wv[7];
    u[0] = gb2[0]; u[1] = u[2] = u[3] = u[4] = 0.0f;
    wv[0] = gb2[1];
#pragma unroll
    for (int m = 1; m < 7; ++m) wv[m] = 0.0f;

    for (int jn = 0; jn < 8; ++jn) {
        float z[7];
        z[0] = gb1[jn];
#pragma unroll
        for (int m = 1; m < 7; ++m) z[m] = 0.0f;
        for (int k = 0; k < 8; ++k) {
            float w = gW1[jn * 8 + k];
#pragma unroll
            for (int m = 0; m < 7; ++m) z[m] = fmaf(w, h[m][k], z[m]);
        }
        float s;
        float t = tanh_fast(z[0], s);
        float t2 = t * t;
        float d1 = s;
        float d2 = -2.0f * t * s;
        float d3 = s * (6.0f * t2 - 2.0f);
        float d4 = t * s * (16.0f - 24.0f * t2);
        float d5 = s * (16.0f + t2 * (-120.0f + 120.0f * t2));
        float d6 = s * t * (-272.0f + t2 * (960.0f - 720.0f * t2));

        float z1 = z[1], z2 = z[2], z3 = z[3], z4 = z[4], z5 = z[5], z6 = z[6];
        float z1_2 = z1 * z1, z1_3 = z1_2 * z1, z1_4 = z1_2 * z1_2;
        float g[7];
        g[0] = t;
        g[1] = d1 * z1;
        g[2] = d1 * z2 + d2 * z1_2;
        g[3] = d1 * z3 + 3.0f * d2 * z1 * z2 + d3 * z1_3;
        g[4] = d1 * z4 + d2 * (4.0f * z1 * z3 + 3.0f * z2 * z2)
             + 6.0f * d3 * z1_2 * z2 + d4 * z1_4;
        g[5] = d1 * z5 + d2 * (5.0f * z1 * z4 + 10.0f * z2 * z3)
             + d3 * (10.0f * z1_2 * z3 + 15.0f * z1 * z2 * z2)
             + 10.0f * d4 * z1_3 * z2 + d5 * z1_4 * z1;
        g[6] = d1 * z6 + d2 * (6.0f * z1 * z5 + 15.0f * z2 * z4 + 10.0f * z3 * z3)
             + d3 * (15.0f * z1_2 * z4 + 60.0f * z1 * z2 * z3 + 15.0f * z2 * z2 * z2)
             + d4 * (20.0f * z1_3 * z3 + 45.0f * z1_2 * z2 * z2)
             + 15.0f * d5 * z1_4 * z2 + d6 * z1_4 * z1_2;

        float wu = gW2[jn];
        float ww = gW2[8 + jn];
#pragma unroll
        for (int m = 0; m < 5; ++m) u[m]  = fmaf(wu, g[m], u[m]);
#pragma unroll
        for (int m = 0; m < 7; ++m) wv[m] = fmaf(ww, g[m], wv[m]);
    }

    float4* tb = &g_table4[j * 4];
    tb[0] = make_float4(u[0],  u[1],  u[2],  u[3]);
    tb[1] = make_float4(u[3],  u[4],  wv[0], wv[1]);
    tb[2] = make_float4(wv[1], wv[2], wv[3], wv[4]);
    tb[3] = make_float4(wv[3], wv[4], wv[5], wv[6]);
}

// ---------------- Kernel B: quad-cooperative, 2-way unrolled ----------------

#define IB      256
#define IGRID   1184   // 8 blocks/SM * 148
#define PS      ((IGRID * IB) >> 2)   // points per grid pass

__device__ __forceinline__ void interp_point(int p, int n, int sub, int lb,
                                             const float* __restrict__ x,
                                             float* __restrict__ out)
{
    int pc = p < n ? p : n - 1;   // clamp so all lanes load safely

    float xv = __ldg(x + pc);
    // round-to-nearest node via magic number (all fixed-latency ops)
    float tm = fmaf(xv, HINV, MAGIC);
    int jn = __float_as_int(tm) & 0xFFFF;       // = j (0..1024)
    float fj = tm - MAGIC;
    float dx = fmaf(fj, -HF, xv);
    float t2 = 0.5f * dx * dx;

    float4 f = __ldg(&g_table4[jn * 4 + sub]);

    // seam for sub1: u2 from sub0's f.z, w2 from sub2's f.y
    float sz = __shfl_sync(0xffffffffu, f.z, lb);
    float sy = __shfl_sync(0xffffffffu, f.y, lb + 2);

    float oA, oB;
    if (sub == 1) {
        oA = fmaf(t2, f.y, fmaf(dx, f.x, sz));   // u_xx
        oB = fmaf(t2, sy,  fmaf(dx, f.w, f.z));  // w
    } else {
        oA = fmaf(t2, f.z, fmaf(dx, f.y, f.x));
        oB = fmaf(t2, f.w, fmaf(dx, f.z, f.y));
    }

    if (p < n) {
        float2* op = reinterpret_cast<float2*>(out + (size_t)p * 8) + sub;
        *op = make_float2(oA, oB);
    }
}

__global__ __launch_bounds__(IB)
void pinn_interp(const float* __restrict__ x, float* __restrict__ out, int n)
{
    const int gid  = blockIdx.x * IB + threadIdx.x;
    const int lane = threadIdx.x & 31;
    const int sub  = lane & 3;
    const int lb   = lane & ~3;

    int p     = gid >> 2;
    int pwarp = p - (lane >> 2);      // warp-uniform base point

    while (pwarp < n) {
        interp_point(p,      n, sub, lb, x, out);
        interp_point(p + PS, n, sub, lb, x, out);
        p     += 2 * PS;
        pwarp += 2 * PS;
    }
}

extern "C" void kernel_launch(void* const* d_in, const int* in_sizes, int n_in,
                              void* d_out, int out_size)
{
    const float* x  = (const float*)d_in[0];
    const float* W0 = (const float*)d_in[1];
    const float* b0 = (const float*)d_in[2];
    const float* W1 = (const float*)d_in[3];
    const float* b1 = (const float*)d_in[4];
    const float* W2 = (const float*)d_in[5];
    const float* b2 = (const float*)d_in[6];
    float* out = (float*)d_out;

    int n = in_sizes[0];

    pinn_build_table<<<(KNODES + 127) / 128, 128>>>(W0, b0, W1, b1, W2, b2);
    pinn_interp<<<IGRID, IB>>>(x, out, n);
}

// round 9
// speedup vs baseline: 1.1130x; 1.1130x over previous
#include <cuda_runtime.h>

// PINN via tabulated jets, quad-cooperative interpolation, 4 pts/quad,
// phase-separated loads for MLP. Kernel A: order-6 jets (fp32, MUFU tanh)
// at 1025 nodes (h=2^-10), 64B/node in 4 overlapping float4 groups.
// Kernel B: 4 lanes per point; batch 4 x-loads then 4 table-loads per lane;
// each lane emits 2 of the 8 outputs (2nd-order Taylor).
// Outputs: [u,u_x,u_xx,w,w_x,w_xx,w_xxx,w_xxxx].

#define KNODES 1025
#define HINV   1024.0f
#define HF     0.0009765625f     // 2^-10 exact
#define MAGIC  12582912.0f       // 1.5 * 2^23

// node j: g0=(u0,u1,u2,u3) g1=(u3,u4,w0,w1) g2=(w1,w2,w3,w4) g3=(w3,w4,w5,w6)
__device__ float4 g_table4[KNODES * 4];

__device__ __forceinline__ float tanh_fast(float z, float& s) {
    float e, r;
    asm("ex2.approx.f32 %0, %1;" : "=f"(e) : "f"(z * 2.8853900817779268f));
    asm("rcp.approx.f32 %0, %1;" : "=f"(r) : "f"(e + 1.0f));
    float t = fmaf(-2.0f, r, 1.0f);
    s = fmaf(-t, t, 1.0f);
    return t;
}

// ---------------- Kernel A: order-6 jets at nodes ----------------

__global__ void pinn_build_table(const float* __restrict__ gW0, const float* __restrict__ gb0,
                                 const float* __restrict__ gW1, const float* __restrict__ gb1,
                                 const float* __restrict__ gW2, const float* __restrict__ gb2)
{
    int j = blockIdx.x * blockDim.x + threadIdx.x;
    if (j >= KNODES) return;

    const float x0 = (float)j * HF;

    float h[7][8];
#pragma unroll
    for (int k = 0; k < 8; ++k) {
        float w = gW0[k];
        float z = fmaf(w, x0, gb0[k]);
        float s;
        float t = tanh_fast(z, s);
        float t2 = t * t;
        float d2 = -2.0f * t * s;
        float d3 = s * (6.0f * t2 - 2.0f);
        float d4 = t * s * (16.0f - 24.0f * t2);
        float d5 = s * (16.0f + t2 * (-120.0f + 120.0f * t2));
        float d6 = s * t * (-272.0f + t2 * (960.0f - 720.0f * t2));
        float w2 = w * w, w3 = w2 * w;
        h[0][k] = t;
        h[1][k] = s  * w;
        h[2][k] = d2 * w2;
        h[3][k] = d3 * w3;
        h[4][k] = d4 * w2 * w2;
        h[5][k] = d5 * w2 * w3;
        h[6][k] = d6 * w3 * w3;
    }

    float u[5]; float wv[7];
    u[0] = gb2[0]; u[1] = u[2] = u[3] = u[4] = 0.0f;
    wv[0] = gb2[1];
#pragma unroll
    for (int m = 1; m < 7; ++m) wv[m] = 0.0f;

    for (int jn = 0; jn < 8; ++jn) {
        float z[7];
        z[0] = gb1[jn];
#pragma unroll
        for (int m = 1; m < 7; ++m) z[m] = 0.0f;
        for (int k = 0; k < 8; ++k) {
            float w = gW1[jn * 8 + k];
#pragma unroll
            for (int m = 0; m < 7; ++m) z[m] = fmaf(w, h[m][k], z[m]);
        }
        float s;
        float t = tanh_fast(z[0], s);
        float t2 = t * t;
        float d1 = s;
        float d2 = -2.0f * t * s;
        float d3 = s * (6.0f * t2 - 2.0f);
        float d4 = t * s * (16.0f - 24.0f * t2);
        float d5 = s * (16.0f + t2 * (-120.0f + 120.0f * t2));
        float d6 = s * t * (-272.0f + t2 * (960.0f - 720.0f * t2));

        float z1 = z[1], z2 = z[2], z3 = z[3], z4 = z[4], z5 = z[5], z6 = z[6];
        float z1_2 = z1 * z1, z1_3 = z1_2 * z1, z1_4 = z1_2 * z1_2;
        float g[7];
        g[0] = t;
        g[1] = d1 * z1;
        g[2] = d1 * z2 + d2 * z1_2;
        g[3] = d1 * z3 + 3.0f * d2 * z1 * z2 + d3 * z1_3;
        g[4] = d1 * z4 + d2 * (4.0f * z1 * z3 + 3.0f * z2 * z2)
             + 6.0f * d3 * z1_2 * z2 + d4 * z1_4;
        g[5] = d1 * z5 + d2 * (5.0f * z1 * z4 + 10.0f * z2 * z3)
             + d3 * (10.0f * z1_2 * z3 + 15.0f * z1 * z2 * z2)
             + 10.0f * d4 * z1_3 * z2 + d5 * z1_4 * z1;
        g[6] = d1 * z6 + d2 * (6.0f * z1 * z5 + 15.0f * z2 * z4 + 10.0f * z3 * z3)
             + d3 * (15.0f * z1_2 * z4 + 60.0f * z1 * z2 * z3 + 15.0f * z2 * z2 * z2)
             + d4 * (20.0f * z1_3 * z3 + 45.0f * z1_2 * z2 * z2)
             + 15.0f * d5 * z1_4 * z2 + d6 * z1_4 * z1_2;

        float wu = gW2[jn];
        float ww = gW2[8 + jn];
#pragma unroll
        for (int m = 0; m < 5; ++m) u[m]  = fmaf(wu, g[m], u[m]);
#pragma unroll
        for (int m = 0; m < 7; ++m) wv[m] = fmaf(ww, g[m], wv[m]);
    }

    float4* tb = &g_table4[j * 4];
    tb[0] = make_float4(u[0],  u[1],  u[2],  u[3]);
    tb[1] = make_float4(u[3],  u[4],  wv[0], wv[1]);
    tb[2] = make_float4(wv[1], wv[2], wv[3], wv[4]);
    tb[3] = make_float4(wv[3], wv[4], wv[5], wv[6]);
}

// ---------------- Kernel B: quad-cooperative, 4 pts/quad, batched loads ----

#define IB   256
#define PPQ  4     // points per quad
// each warp covers 32 consecutive points; each block 8 warps = 256 points

__global__ __launch_bounds__(IB)
void pinn_interp(const float* __restrict__ x, float* __restrict__ out, int n)
{
    const int tid   = blockIdx.x * IB + threadIdx.x;
    const int lane  = threadIdx.x & 31;
    const int sub   = lane & 3;
    const int lb    = lane & ~3;
    const int quad  = lane >> 2;              // 0..7
    const int wbase = (tid >> 5) * 32;        // first point of this warp

    // ---- Phase 1: batched x loads (4 independent) ----
    float xv[PPQ];
#pragma unroll
    for (int k = 0; k < PPQ; ++k) {
        int p  = wbase + 8 * k + quad;
        int pc = p < n ? p : n - 1;
        xv[k] = __ldg(x + pc);
    }

    // ---- Phase 2: index math + batched table loads (4 independent) ----
    int   jn[PPQ];
    float dx[PPQ], t2[PPQ];
#pragma unroll
    for (int k = 0; k < PPQ; ++k) {
        float tm = fmaf(xv[k], HINV, MAGIC);
        jn[k] = __float_as_int(tm) & 0xFFFF;
        float fj = tm - MAGIC;
        dx[k] = fmaf(fj, -HF, xv[k]);
        t2[k] = 0.5f * dx[k] * dx[k];
    }
    float4 f[PPQ];
#pragma unroll
    for (int k = 0; k < PPQ; ++k)
        f[k] = __ldg(&g_table4[jn[k] * 4 + sub]);

    // ---- Phase 3: seam shuffles, Taylor, coalesced stores ----
#pragma unroll
    for (int k = 0; k < PPQ; ++k) {
        float sz = __shfl_sync(0xffffffffu, f[k].z, lb);      // u2 from sub0
        float sy = __shfl_sync(0xffffffffu, f[k].y, lb + 2);  // w2 from sub2

        float oA, oB;
        if (sub == 1) {
            oA = fmaf(t2[k], f[k].y, fmaf(dx[k], f[k].x, sz));  // u_xx
            oB = fmaf(t2[k], sy,     fmaf(dx[k], f[k].w, f[k].z)); // w
        } else {
            oA = fmaf(t2[k], f[k].z, fmaf(dx[k], f[k].y, f[k].x));
            oB = fmaf(t2[k], f[k].w, fmaf(dx[k], f[k].z, f[k].y));
        }

        int p = wbase + 8 * k + quad;
        if (p < n) {
            float2* op = reinterpret_cast<float2*>(out + (size_t)p * 8) + sub;
            *op = make_float2(oA, oB);
        }
    }
}

extern "C" void kernel_launch(void* const* d_in, const int* in_sizes, int n_in,
                              void* d_out, int out_size)
{
    const float* x  = (const float*)d_in[0];
    const float* W0 = (const float*)d_in[1];
    const float* b0 = (const float*)d_in[2];
    const float* W1 = (const float*)d_in[3];
    const float* b1 = (const float*)d_in[4];
    const float* W2 = (const float*)d_in[5];
    const float* b2 = (const float*)d_in[6];
    float* out = (float*)d_out;

    int n = in_sizes[0];
    int pts_per_block = IB / 4 * PPQ * 4 / 4;   // 256 points per 256-thread block
    (void)pts_per_block;
    int blocks = (n + 255) / 256;               // 256 points per block

    pinn_build_table<<<(KNODES + 127) / 128, 128>>>(W0, b0, W1, b1, W2, b2);
    pinn_interp<<<blocks, IB>>>(x, out, n);
}